// round 9
// baseline (speedup 1.0000x reference)
#include <cuda_runtime.h>
#include <cuda_bf16.h>
#include <cstdint>

#define NN 100000
#define NE 800000
#define H  64
#define NT 256
#define UP 132
#define NBLK 391
#define BPITCH 72   // bf16 row pitch for mma tiles (conflict-free ldmatrix)

#define SMEM_UPD   ((8192 + 128 * UP) * 4)
#define SMEM_PROJT (4 * 128 * BPITCH * 2)   // AH, AL, BH, BL tiles (bf16)

// Scratch (device globals: allocation-free rule)
__device__ __align__(16) float g_x[(size_t)NN * H];
__device__ __align__(16) float g_p1[(size_t)NN * H];
__device__ __align__(16) float g_p2[(size_t)NN * H];
__device__ __align__(16) float g_agg[(size_t)NN * H];
__device__ __align__(16) float g_wpu[3 * 8192];                    // upd W pair-packed
__device__ __align__(16) __nv_bfloat16 g_bh[3 * 128 * BPITCH];     // proj B hi, [C][k] padded
__device__ __align__(16) __nv_bfloat16 g_bl[3 * 128 * BPITCH];     // proj B lo
__device__ int g_deg[NN];
__device__ int g_off[NN + 1];
__device__ int g_cur[NN];
__device__ int g_csr[NE];
__device__ int g_bsum[NBLK];
__device__ int g_boff[NBLK];
__device__ float g_sum[H];
__device__ unsigned g_maxb[H];

// ---------- packed f32x2 helpers (upd GEMM) ----------
__device__ __forceinline__ uint64_t pk2(float lo, float hi) {
    uint64_t r;
    asm("mov.b64 %0, {%1, %2};" : "=l"(r) : "r"(__float_as_uint(lo)), "r"(__float_as_uint(hi)));
    return r;
}
__device__ __forceinline__ void fma2(uint64_t& acc, uint64_t w, uint64_t p) {
    asm("fma.rn.f32x2 %0, %1, %2, %0;" : "+l"(acc) : "l"(w), "l"(p));
}
__device__ __forceinline__ float unpk_sum(uint64_t v) {
    unsigned a, b;
    asm("mov.b64 {%0, %1}, %2;" : "=r"(a), "=r"(b) : "l"(v));
    return __uint_as_float(a) + __uint_as_float(b);
}
__device__ __forceinline__ unsigned encf(float f) {
    unsigned u = __float_as_uint(f);
    return (u & 0x80000000u) ? ~u : (u | 0x80000000u);
}
__device__ __forceinline__ float decf(unsigned u) {
    return (u & 0x80000000u) ? __uint_as_float(u & 0x7FFFFFFFu) : __uint_as_float(~u);
}

// ---------- mma.sync helpers (baseline PTX ISA; no 'a' features) ----------
__device__ __forceinline__ void ldsm4(unsigned& r0, unsigned& r1, unsigned& r2, unsigned& r3,
                                      uint32_t addr) {
    asm volatile("ldmatrix.sync.aligned.m8n8.x4.shared.b16 {%0,%1,%2,%3}, [%4];"
                 : "=r"(r0), "=r"(r1), "=r"(r2), "=r"(r3) : "r"(addr));
}
__device__ __forceinline__ void ldsm2(unsigned& r0, unsigned& r1, uint32_t addr) {
    asm volatile("ldmatrix.sync.aligned.m8n8.x2.shared.b16 {%0,%1}, [%2];"
                 : "=r"(r0), "=r"(r1) : "r"(addr));
}
__device__ __forceinline__ void mma16816(float* c, const unsigned* a, const unsigned* b) {
    asm volatile("mma.sync.aligned.m16n8k16.row.col.f32.bf16.bf16.f32 "
                 "{%0,%1,%2,%3}, {%4,%5,%6,%7}, {%8,%9}, {%0,%1,%2,%3};"
                 : "+f"(c[0]), "+f"(c[1]), "+f"(c[2]), "+f"(c[3])
                 : "r"(a[0]), "r"(a[1]), "r"(a[2]), "r"(a[3]), "r"(b[0]), "r"(b[1]));
}

// ---------- setup ----------
__global__ void k_embed(const int* __restrict__ ti, const float* __restrict__ et) {
    int i = blockIdx.x * blockDim.x + threadIdx.x;
    int stride = gridDim.x * blockDim.x;
    for (int lin = i; lin < NN * 16; lin += stride) {
        int n = lin >> 4, q = lin & 15;
        ((float4*)g_x)[lin] = ((const float4*)et)[ti[n] * 16 + q];
    }
    for (int n = i; n < NN; n += stride) g_deg[n] = 0;
    if (i < H) { g_sum[i] = 0.f; g_maxb[i] = 0u; }
}

__global__ void k_hist(const int* __restrict__ edges) {
    int i = blockIdx.x * blockDim.x + threadIdx.x;
    int stride = gridDim.x * blockDim.x;
    for (int e = i; e < NE; e += stride)
        atomicAdd(&g_deg[((const int2*)edges)[e].y], 1);
}

// ---------- weight prepack ----------
// proj B (bf16 hi/lo, n-major [C][k], pitch 72): B[C][k] = msg_w[k + (C&64)][C&63]
// upd W pair-packed fp32: g_wpu[(t*64 + c)*2 + s] = upd_w[2t+s][c]
__global__ void k_prepack(const float* __restrict__ msg_w, const float* __restrict__ upd_w) {
    int i = blockIdx.x * blockDim.x + threadIdx.x;
    int stride = gridDim.x * blockDim.x;
    for (int idx = i; idx < 3 * 128 * BPITCH; idx += stride) {  // include pad: zero it
        int l = idx / (128 * BPITCH), r = idx % (128 * BPITCH);
        int C = r / BPITCH, k = r % BPITCH;
        __nv_bfloat16 h = __float2bfloat16(0.f), lo = __float2bfloat16(0.f);
        if (k < 64) {
            float v = msg_w[l * 8192 + (k + (C & 64)) * 64 + (C & 63)];
            h = __float2bfloat16(v);
            lo = __float2bfloat16(v - __bfloat162float(h));
        }
        g_bh[idx] = h;
        g_bl[idx] = lo;
    }
    for (int idx = i; idx < 3 * 8192; idx += stride) {
        int l = idx / 8192, r = idx % 8192;
        int s = r & 1, tc = r >> 1;
        int c = tc & 63, t = tc >> 6;
        g_wpu[idx] = upd_w[l * 8192 + (2 * t + s) * 64 + c];
    }
}

// ---------- exclusive scan ----------
__global__ void k_scan1() {
    __shared__ int s[256];
    int t = threadIdx.x;
    int i = blockIdx.x * 256 + t;
    int v = (i < NN) ? g_deg[i] : 0;
    s[t] = v;
    __syncthreads();
    #pragma unroll
    for (int d = 1; d < 256; d <<= 1) {
        int tv = (t >= d) ? s[t - d] : 0;
        __syncthreads();
        s[t] += tv;
        __syncthreads();
    }
    if (i < NN) g_off[i] = s[t] - v;
    if (t == 255) g_bsum[blockIdx.x] = s[255];
}

__global__ void k_scan2() {
    __shared__ int s[512];
    int t = threadIdx.x;
    int v = (t < NBLK) ? g_bsum[t] : 0;
    s[t] = v;
    __syncthreads();
    #pragma unroll
    for (int d = 1; d < 512; d <<= 1) {
        int tv = (t >= d) ? s[t - d] : 0;
        __syncthreads();
        s[t] += tv;
        __syncthreads();
    }
    if (t < NBLK) g_boff[t] = s[t] - v;
}

__global__ void k_scan3() {
    int i = blockIdx.x * blockDim.x + threadIdx.x;
    if (i < NN) {
        int val = g_off[i] + g_boff[i >> 8];
        g_off[i] = val;
        g_cur[i] = val;
    }
    if (i == 0) g_off[NN] = NE;
}

__global__ void k_scatter(const int* __restrict__ edges) {
    int e = blockIdx.x * blockDim.x + threadIdx.x;
    if (e < NE) {
        int2 ed = ((const int2*)edges)[e];
        int pos = atomicAdd(&g_cur[ed.y], 1);
        g_csr[pos] = ed.x;
    }
}

// ---------- tensor-core (mma.sync) projection ----------
// D[128 rows][128 cols] = Xtile[128][64] @ B^T; cols 0-63 -> P1, 64-127 -> P2 (+bias)
// bf16 hi/lo split: 3 accumulating mmas (AhBh + AhBl + AlBh), fp32 accumulators.
__global__ __launch_bounds__(256, 2) void k_proj_t(int layer, const float* __restrict__ msg_b) {
    extern __shared__ char smc[];
    __nv_bfloat16* AH = (__nv_bfloat16*)smc;          // [128][72]
    __nv_bfloat16* AL = AH + 128 * BPITCH;
    __nv_bfloat16* BH = AL + 128 * BPITCH;
    __nv_bfloat16* BL = BH + 128 * BPITCH;

    const int tid = threadIdx.x;
    const int w = tid >> 5, l = tid & 31;

    // stage B (prepacked, padded) into smem: 128*72*2 bytes = 1152 float4 per tile
    {
        const float4* sh = (const float4*)(g_bh + layer * 128 * BPITCH);
        const float4* sl = (const float4*)(g_bl + layer * 128 * BPITCH);
        float4* dh = (float4*)BH;
        float4* dl = (float4*)BL;
        for (int i = tid; i < 1152; i += 256) { dh[i] = sh[i]; dl[i] = sl[i]; }
    }

    // bias pairs for P2 columns owned by this lane
    float2 bias2[8];
    #pragma unroll
    for (int i = 0; i < 8; i++) {
        int c = i * 8 + (l & 3) * 2;
        bias2[i] = make_float2(msg_b[c], msg_b[c + 1]);
    }

    // ldmatrix lane addresses (within-tile byte offsets)
    const uint32_t a_off = (uint32_t)(((w << 4) + (l & 15)) * BPITCH * 2) + ((l >> 4) ? 16u : 0u);
    const uint32_t b_off = (uint32_t)((l & 7) * BPITCH * 2) + (((l >> 3) & 1) ? 16u : 0u);
    const uint32_t aH = (uint32_t)__cvta_generic_to_shared(AH) + a_off;
    const uint32_t aL = (uint32_t)__cvta_generic_to_shared(AL) + a_off;
    const uint32_t bH = (uint32_t)__cvta_generic_to_shared(BH) + b_off;
    const uint32_t bL = (uint32_t)__cvta_generic_to_shared(BL) + b_off;

    const int ntiles = (NN + 127) / 128;
    for (int tile = blockIdx.x; tile < ntiles; tile += gridDim.x) {
        const int base = tile * 128;

        // convert x tile -> bf16 hi/lo, [128][72] row-major (only k<64 written/read)
        for (int p = tid; p < 4096; p += 256) {
            int r = p >> 5, kp = p & 31;
            int gn = base + r; if (gn >= NN) gn = NN - 1;
            float2 v = *(const float2*)(g_x + (size_t)gn * H + 2 * kp);
            __nv_bfloat16 h0 = __float2bfloat16(v.x), h1 = __float2bfloat16(v.y);
            __nv_bfloat16 l0 = __float2bfloat16(v.x - __bfloat162float(h0));
            __nv_bfloat16 l1 = __float2bfloat16(v.y - __bfloat162float(h1));
            *(__nv_bfloat162*)(AH + r * BPITCH + 2 * kp) = __halves2bfloat162(h0, h1);
            *(__nv_bfloat162*)(AL + r * BPITCH + 2 * kp) = __halves2bfloat162(l0, l1);
        }
        __syncthreads();

        float C[16][4];
        #pragma unroll
        for (int nt = 0; nt < 16; nt++) {
            C[nt][0] = 0.f; C[nt][1] = 0.f; C[nt][2] = 0.f; C[nt][3] = 0.f;
        }

        #pragma unroll
        for (int ks = 0; ks < 4; ks++) {
            unsigned Ah[4], Al4[4];
            ldsm4(Ah[0], Ah[1], Ah[2], Ah[3], aH + ks * 32);
            ldsm4(Al4[0], Al4[1], Al4[2], Al4[3], aL + ks * 32);
            #pragma unroll
            for (int nt = 0; nt < 16; nt++) {
                unsigned Bh[2], Bl[2];
                ldsm2(Bh[0], Bh[1], bH + nt * 8 * BPITCH * 2 + ks * 32);
                ldsm2(Bl[0], Bl[1], bL + nt * 8 * BPITCH * 2 + ks * 32);
                mma16816(C[nt], Ah, Bh);
                mma16816(C[nt], Ah, Bl);
                mma16816(C[nt], Al4, Bh);
            }
        }

        // store: rows r0, r0+8; lane owns col pair (l&3)*2 within each 8-col group
        int r0 = base + (w << 4) + (l >> 2);
        int r1 = r0 + 8;
        int cc = (l & 3) * 2;
        #pragma unroll
        for (int nt = 0; nt < 8; nt++) {
            int col = nt * 8 + cc;
            if (r0 < NN) *(float2*)(g_p1 + (size_t)r0 * H + col) = make_float2(C[nt][0], C[nt][1]);
            if (r1 < NN) *(float2*)(g_p1 + (size_t)r1 * H + col) = make_float2(C[nt][2], C[nt][3]);
        }
        #pragma unroll
        for (int nt = 8; nt < 16; nt++) {
            int col = (nt - 8) * 8 + cc;
            float2 bb = bias2[nt - 8];
            if (r0 < NN) *(float2*)(g_p2 + (size_t)r0 * H + col) =
                make_float2(C[nt][0] + bb.x, C[nt][1] + bb.y);
            if (r1 < NN) *(float2*)(g_p2 + (size_t)r1 * H + col) =
                make_float2(C[nt][2] + bb.x, C[nt][3] + bb.y);
        }
        __syncthreads();   // all ldmatrix reads done before next tile's conversion
    }
}

// ---------- CSR edge pass: agg[n] = mean of relu(P1[src] + P2[n]) ----------
__global__ __launch_bounds__(NT) void k_edge() {
    int idx = blockIdx.x * NT + threadIdx.x;
    int n = idx >> 3, q = idx & 7;
    int s0 = g_off[n], s1 = g_off[n + 1];
    const float4* p2 = (const float4*)(g_p2 + (size_t)n * H) + q * 2;
    float4 b0 = p2[0], b1 = p2[1];
    float a[8] = {0.f, 0.f, 0.f, 0.f, 0.f, 0.f, 0.f, 0.f};
    for (int i = s0; i < s1; i++) {
        int src = g_csr[i];
        const float4* p1 = (const float4*)(g_p1 + (size_t)src * H) + q * 2;
        float4 c0 = p1[0], c1 = p1[1];
        a[0] += fmaxf(c0.x + b0.x, 0.f); a[1] += fmaxf(c0.y + b0.y, 0.f);
        a[2] += fmaxf(c0.z + b0.z, 0.f); a[3] += fmaxf(c0.w + b0.w, 0.f);
        a[4] += fmaxf(c1.x + b1.x, 0.f); a[5] += fmaxf(c1.y + b1.y, 0.f);
        a[6] += fmaxf(c1.z + b1.z, 0.f); a[7] += fmaxf(c1.w + b1.w, 0.f);
    }
    float ic = 1.0f / fmaxf((float)(s1 - s0), 1.0f);
    float4* dst = (float4*)(g_agg + (size_t)n * H + q * 8);
    dst[0] = make_float4(a[0] * ic, a[1] * ic, a[2] * ic, a[3] * ic);
    dst[1] = make_float4(a[4] * ic, a[5] * ic, a[6] * ic, a[7] * ic);
}

// ---------- node update GEMM + residual + LayerNorm ----------
// k-pair packed, TR=128. thread: 8 rows (rg + 16j) x 4 cols {c2,c2+1,32+c2,33+c2}.
__global__ __launch_bounds__(NT, 2) void k_upd(const float* __restrict__ Wp,
                                               const float* __restrict__ B,
                                               const float* __restrict__ lng,
                                               const float* __restrict__ lnb) {
    extern __shared__ float sm[];
    float* Wsh  = sm;            // 8192 pair-packed
    float* insh = sm + 8192;     // 128 * UP

    const int tid = threadIdx.x;
    for (int i = tid; i < 2048; i += NT) ((float4*)Wsh)[i] = ((const float4*)Wp)[i];

    const int cg = tid & 15, rg = tid >> 4;
    const int c2 = cg * 2;

    const float bb0 = B[c2], bb1 = B[c2 + 1], bb2 = B[32 + c2], bb3 = B[33 + c2];
    const float gg0 = lng[c2], gg1 = lng[c2 + 1], gg2 = lng[32 + c2], gg3 = lng[33 + c2];
    const float be0 = lnb[c2], be1 = lnb[c2 + 1], be2 = lnb[32 + c2], be3 = lnb[33 + c2];

    const int l_nl = tid >> 5, l_q = tid & 31;
    const int ntiles = (NN + 127) / 128;

    for (int tile = blockIdx.x; tile < ntiles; tile += gridDim.x) {
        const int base = tile * 128;
        #pragma unroll
        for (int r = 0; r < 16; r++) {
            int nl = l_nl + r * 8;
            int gn = base + nl; if (gn >= NN) gn = NN - 1;
            float4 v = (l_q < 16) ? ((const float4*)g_x)[gn * 16 + l_q]
                                  : ((const float4*)g_agg)[gn * 16 + (l_q - 16)];
            ((float4*)(insh + nl * UP))[l_q] = v;
        }
        __syncthreads();

        uint64_t acc[8][4];
        {
            uint64_t a0 = pk2(bb0, 0.f), a1 = pk2(bb1, 0.f);
            uint64_t a2 = pk2(bb2, 0.f), a3 = pk2(bb3, 0.f);
            #pragma unroll
            for (int j = 0; j < 8; j++) {
                acc[j][0] = a0; acc[j][1] = a1; acc[j][2] = a2; acc[j][3] = a3;
            }
        }

        #pragma unroll 2
        for (int t2 = 0; t2 < 32; t2++) {
            ulonglong2 xv[8];
            #pragma unroll
            for (int j = 0; j < 8; j++)
                xv[j] = *(const ulonglong2*)(insh + (rg + 16 * j) * UP + 4 * t2);
            #pragma unroll
            for (int p = 0; p < 2; p++) {
                int t = 2 * t2 + p;
                ulonglong2 w1 = *(const ulonglong2*)(Wsh + (t * 64 + c2) * 2);
                ulonglong2 w2 = *(const ulonglong2*)(Wsh + (t * 64 + 32 + c2) * 2);
                #pragma unroll
                for (int j = 0; j < 8; j++) {
                    uint64_t x2 = p ? xv[j].y : xv[j].x;
                    fma2(acc[j][0], w1.x, x2); fma2(acc[j][1], w1.y, x2);
                    fma2(acc[j][2], w2.x, x2); fma2(acc[j][3], w2.y, x2);
                }
            }
        }

        #pragma unroll
        for (int j = 0; j < 8; j++) {
            int row = rg + 16 * j;
            int gn = base + row;
            const float* xo = insh + row * UP;
            float h0 = fmaxf(unpk_sum(acc[j][0]), 0.f) + xo[c2];
            float h1 = fmaxf(unpk_sum(acc[j][1]), 0.f) + xo[c2 + 1];
            float h2 = fmaxf(unpk_sum(acc[j][2]), 0.f) + xo[32 + c2];
            float h3 = fmaxf(unpk_sum(acc[j][3]), 0.f) + xo[33 + c2];
            float s1 = h0 + h1 + h2 + h3;
            float s2 = h0 * h0 + h1 * h1 + h2 * h2 + h3 * h3;
            #pragma unroll
            for (int d = 1; d < 16; d <<= 1) {
                s1 += __shfl_xor_sync(0xFFFFFFFFu, s1, d);
                s2 += __shfl_xor_sync(0xFFFFFFFFu, s2, d);
            }
            float mu  = s1 * 0.015625f;
            float var = s2 * 0.015625f - mu * mu;
            float sc  = rsqrtf(fmaxf(var, 0.f) + 1e-5f);
            if (gn < NN) {
                float o0 = (h0 - mu) * sc * gg0 + be0;
                float o1 = (h1 - mu) * sc * gg1 + be1;
                float o2 = (h2 - mu) * sc * gg2 + be2;
                float o3 = (h3 - mu) * sc * gg3 + be3;
                *(float2*)(g_x + (size_t)gn * H + c2)      = make_float2(o0, o1);
                *(float2*)(g_x + (size_t)gn * H + 32 + c2) = make_float2(o2, o3);
            }
        }
        __syncthreads();
    }
}

// ---------- final mean/max over nodes ----------
__global__ void k_reduce() {
    __shared__ float rs[4][64];
    __shared__ float rm[4][64];
    int j = threadIdx.x & 63, g = threadIdx.x >> 6;
    float s = 0.f, m = -3.402823466e38f;
    for (int n = blockIdx.x * 4 + g; n < NN; n += gridDim.x * 4) {
        float v = g_x[(size_t)n * H + j];
        s += v; m = fmaxf(m, v);
    }
    rs[g][j] = s; rm[g][j] = m;
    __syncthreads();
    if (g == 0) {
        #pragma unroll
        for (int i = 1; i < 4; i++) { s += rs[i][j]; m = fmaxf(m, rm[i][j]); }
        atomicAdd(&g_sum[j], s);
        atomicMax(&g_maxb[j], encf(m));
    }
}

__global__ void k_final(float* out) {
    int t = threadIdx.x;
    if (t < 64) out[t] = g_sum[t] * (1.0f / NN);
    else        out[t] = decf(g_maxb[t - 64]);
}

// ---------- launch ----------
extern "C" void kernel_launch(void* const* d_in, const int* in_sizes, int n_in,
                              void* d_out, int out_size) {
    const int*   ti    = (const int*)d_in[0];
    const int*   edges = (const int*)d_in[1];
    const float* et    = (const float*)d_in[2];
    const float* msg_w = (const float*)d_in[3];
    const float* msg_b = (const float*)d_in[4];
    const float* upd_w = (const float*)d_in[5];
    const float* upd_b = (const float*)d_in[6];
    const float* lng   = (const float*)d_in[7];
    const float* lnb   = (const float*)d_in[8];
    float* out = (float*)d_out;

    cudaFuncSetAttribute(k_proj_t, cudaFuncAttributeMaxDynamicSharedMemorySize, SMEM_PROJT);
    cudaFuncSetAttribute(k_upd,    cudaFuncAttributeMaxDynamicSharedMemorySize, SMEM_UPD);

    static float* wpu_base = nullptr;
    if (!wpu_base) cudaGetSymbolAddress((void**)&wpu_base, g_wpu);

    k_embed<<<512, 256>>>(ti, et);
    k_hist<<<512, 256>>>(edges);
    k_prepack<<<96, 256>>>(msg_w, upd_w);

    // layer-0 proj placed 4th so ncu (-s5 -c1) profiles it
    k_proj_t<<<296, 256, SMEM_PROJT>>>(0, msg_b);

    k_scan1<<<NBLK, 256>>>();
    k_scan2<<<1, 512>>>();
    k_scan3<<<392, 256>>>();
    k_scatter<<<(NE + 255) / 256, 256>>>(edges);

    for (int l = 0; l < 3; l++) {
        if (l > 0) k_proj_t<<<296, 256, SMEM_PROJT>>>(l, msg_b + l * 64);
        k_edge<<<NN * 8 / NT, NT>>>();
        k_upd<<<296, NT, SMEM_UPD>>>(wpu_base + l * 8192, upd_b + l * 64,
                                     lng + l * 64, lnb + l * 64);
    }

    k_reduce<<<296, 256>>>();
    k_final<<<1, 128>>>(out);
}

// round 10
// speedup vs baseline: 1.6371x; 1.6371x over previous
#include <cuda_runtime.h>
#include <cuda_bf16.h>
#include <cstdint>

#define NN 100000
#define NE 800000
#define H  64
#define NT 256
#define NBLK 391
#define PPIT 144   // proj smem row pitch bytes (72 bf16)
#define UPIT 272   // upd smem row pitch bytes (136 bf16)

#define SMEM_PROJT (4 * 128 * PPIT)                         // AH AL BH BL
#define SMEM_UPDT  (2 * 128 * UPIT + 2 * 64 * UPIT + 768)   // AH AL BH BL + params

// Scratch (device globals: allocation-free rule)
__device__ __align__(16) float g_x[(size_t)NN * H];
__device__ __align__(16) float g_p1[(size_t)NN * H];
__device__ __align__(16) float g_p2[(size_t)NN * H];
__device__ __align__(16) __nv_bfloat162 g_xh[(size_t)NN * 32];
__device__ __align__(16) __nv_bfloat162 g_xl[(size_t)NN * 32];
__device__ __align__(16) __nv_bfloat162 g_ah[(size_t)NN * 32];
__device__ __align__(16) __nv_bfloat162 g_al[(size_t)NN * 32];
__device__ __align__(16) __nv_bfloat16 g_bh[3 * 128 * 72];   // proj W hi [C][k] pitch 72
__device__ __align__(16) __nv_bfloat16 g_bl[3 * 128 * 72];
__device__ __align__(16) __nv_bfloat16 g_uh[3 * 64 * 136];   // upd W hi [C][k] pitch 136
__device__ __align__(16) __nv_bfloat16 g_ul[3 * 64 * 136];
__device__ int g_deg[NN];
__device__ int g_off[NN + 1];
__device__ int g_cur[NN];
__device__ int g_csr[NE];
__device__ int g_bsum[NBLK];
__device__ int g_boff[NBLK];
__device__ float g_sum[H];
__device__ unsigned g_maxb[H];

// ---------- helpers ----------
__device__ __forceinline__ unsigned encf(float f) {
    unsigned u = __float_as_uint(f);
    return (u & 0x80000000u) ? ~u : (u | 0x80000000u);
}
__device__ __forceinline__ float decf(unsigned u) {
    return (u & 0x80000000u) ? __uint_as_float(u & 0x7FFFFFFFu) : __uint_as_float(~u);
}
__device__ __forceinline__ void split2(float a, float b, __nv_bfloat162& h, __nv_bfloat162& lo) {
    __nv_bfloat16 ha = __float2bfloat16(a), hb = __float2bfloat16(b);
    h = __halves2bfloat162(ha, hb);
    lo = __halves2bfloat162(__float2bfloat16(a - __bfloat162float(ha)),
                            __float2bfloat16(b - __bfloat162float(hb)));
}
__device__ __forceinline__ void ldsm4(unsigned& r0, unsigned& r1, unsigned& r2, unsigned& r3,
                                      uint32_t addr) {
    asm volatile("ldmatrix.sync.aligned.m8n8.x4.shared.b16 {%0,%1,%2,%3}, [%4];"
                 : "=r"(r0), "=r"(r1), "=r"(r2), "=r"(r3) : "r"(addr));
}
__device__ __forceinline__ void mma16816(float* c, const unsigned* a, const unsigned* b) {
    asm volatile("mma.sync.aligned.m16n8k16.row.col.f32.bf16.bf16.f32 "
                 "{%0,%1,%2,%3}, {%4,%5,%6,%7}, {%8,%9}, {%0,%1,%2,%3};"
                 : "+f"(c[0]), "+f"(c[1]), "+f"(c[2]), "+f"(c[3])
                 : "r"(a[0]), "r"(a[1]), "r"(a[2]), "r"(a[3]), "r"(b[0]), "r"(b[1]));
}

// ---------- setup ----------
__global__ void k_embed(const int* __restrict__ ti, const float* __restrict__ et) {
    int i = blockIdx.x * blockDim.x + threadIdx.x;
    int stride = gridDim.x * blockDim.x;
    for (int lin = i; lin < NN * 16; lin += stride) {
        int n = lin >> 4, q = lin & 15;
        float4 v = ((const float4*)et)[ti[n] * 16 + q];
        ((float4*)g_x)[lin] = v;
        __nv_bfloat162 h0, l0, h1, l1;
        split2(v.x, v.y, h0, l0);
        split2(v.z, v.w, h1, l1);
        g_xh[lin * 2] = h0; g_xh[lin * 2 + 1] = h1;
        g_xl[lin * 2] = l0; g_xl[lin * 2 + 1] = l1;
    }
    for (int n = i; n < NN; n += stride) g_deg[n] = 0;
    if (i < H) { g_sum[i] = 0.f; g_maxb[i] = 0u; }
}

__global__ void k_hist(const int* __restrict__ edges) {
    int i = blockIdx.x * blockDim.x + threadIdx.x;
    int stride = gridDim.x * blockDim.x;
    for (int e = i; e < NE; e += stride)
        atomicAdd(&g_deg[((const int2*)edges)[e].y], 1);
}

// ---------- weight prepack (bf16 hi/lo, n-major [C][k], padded pitch) ----------
__global__ void k_prepack(const float* __restrict__ msg_w, const float* __restrict__ upd_w) {
    int i = blockIdx.x * blockDim.x + threadIdx.x;
    int stride = gridDim.x * blockDim.x;
    for (int idx = i; idx < 3 * 128 * 72; idx += stride) {
        int l = idx / (128 * 72), r = idx % (128 * 72);
        int C = r / 72, k = r % 72;
        __nv_bfloat16 h = __float2bfloat16(0.f), lo = h;
        if (k < 64) {
            float v = msg_w[l * 8192 + (k + (C & 64)) * 64 + (C & 63)];
            h = __float2bfloat16(v);
            lo = __float2bfloat16(v - __bfloat162float(h));
        }
        g_bh[idx] = h; g_bl[idx] = lo;
    }
    for (int idx = i; idx < 3 * 64 * 136; idx += stride) {
        int l = idx / (64 * 136), r = idx % (64 * 136);
        int C = r / 136, k = r % 136;
        __nv_bfloat16 h = __float2bfloat16(0.f), lo = h;
        if (k < 128) {
            float v = upd_w[l * 8192 + k * 64 + C];
            h = __float2bfloat16(v);
            lo = __float2bfloat16(v - __bfloat162float(h));
        }
        g_uh[idx] = h; g_ul[idx] = lo;
    }
}

// ---------- exclusive scan ----------
__global__ void k_scan1() {
    __shared__ int s[256];
    int t = threadIdx.x;
    int i = blockIdx.x * 256 + t;
    int v = (i < NN) ? g_deg[i] : 0;
    s[t] = v;
    __syncthreads();
    #pragma unroll
    for (int d = 1; d < 256; d <<= 1) {
        int tv = (t >= d) ? s[t - d] : 0;
        __syncthreads();
        s[t] += tv;
        __syncthreads();
    }
    if (i < NN) g_off[i] = s[t] - v;
    if (t == 255) g_bsum[blockIdx.x] = s[255];
}

__global__ void k_scan2() {
    __shared__ int s[512];
    int t = threadIdx.x;
    int v = (t < NBLK) ? g_bsum[t] : 0;
    s[t] = v;
    __syncthreads();
    #pragma unroll
    for (int d = 1; d < 512; d <<= 1) {
        int tv = (t >= d) ? s[t - d] : 0;
        __syncthreads();
        s[t] += tv;
        __syncthreads();
    }
    if (t < NBLK) g_boff[t] = s[t] - v;
}

__global__ void k_scan3() {
    int i = blockIdx.x * blockDim.x + threadIdx.x;
    if (i < NN) {
        int val = g_off[i] + g_boff[i >> 8];
        g_off[i] = val;
        g_cur[i] = val;
    }
    if (i == 0) g_off[NN] = NE;
}

__global__ void k_scatter(const int* __restrict__ edges) {
    int e = blockIdx.x * blockDim.x + threadIdx.x;
    if (e < NE) {
        int2 ed = ((const int2*)edges)[e];
        int pos = atomicAdd(&g_cur[ed.y], 1);
        g_csr[pos] = ed.x;
    }
}

// ---------- tensor-core projection ----------
// D[128][128] = X[128][64] @ B^T; cols 0-63 -> P1, 64-127 -> P2 (+bias). 3-mma bf16 split.
__global__ __launch_bounds__(256, 2) void k_proj_t(int layer, const float* __restrict__ msg_b) {
    extern __shared__ char smc[];
    char* AH = smc;
    char* AL = AH + 128 * PPIT;
    char* BH = AL + 128 * PPIT;
    char* BL = BH + 128 * PPIT;

    const int tid = threadIdx.x;
    const int w = tid >> 5, l = tid & 31;

    // stage B (prepacked, pitch 72 bf16 = 18KB per tile = 1152 uint4)
    {
        const uint4* sh = (const uint4*)(g_bh + layer * 128 * 72);
        const uint4* sl = (const uint4*)(g_bl + layer * 128 * 72);
        for (int i = tid; i < 1152; i += 256) {
            ((uint4*)BH)[i] = sh[i];
            ((uint4*)BL)[i] = sl[i];
        }
    }
    // bias pairs for this lane's P2 cols
    float2 bias2[8];
    #pragma unroll
    for (int i = 0; i < 8; i++) bias2[i] = *(const float2*)(msg_b + i * 8 + (l & 3) * 2);

    const uint32_t a_loff = (uint32_t)(((w << 4) + (l & 15)) * PPIT) + ((l >> 4) ? 16u : 0u);
    const uint32_t b_loff = (uint32_t)((l & 7) * PPIT) + (((l >> 3) & 1) ? 16u : 0u)
                          + (((l >> 4) & 1) ? 8u * PPIT : 0u);
    const uint32_t aH = (uint32_t)__cvta_generic_to_shared(AH) + a_loff;
    const uint32_t aL = (uint32_t)__cvta_generic_to_shared(AL) + a_loff;
    const uint32_t bH = (uint32_t)__cvta_generic_to_shared(BH) + b_loff;
    const uint32_t bL = (uint32_t)__cvta_generic_to_shared(BL) + b_loff;

    const uint4* xh4 = (const uint4*)g_xh;   // NN * 8 chunks of 16B
    const uint4* xl4 = (const uint4*)g_xl;

    const int ntiles = (NN + 127) / 128;
    for (int tile = blockIdx.x; tile < ntiles; tile += gridDim.x) {
        const int base = tile * 128;

        // stage A: pure 16B copies (1024 chunks each)
        for (int i = tid; i < 1024; i += 256) {
            int r = i >> 3, q = i & 7;
            int gn = base + r; if (gn >= NN) gn = NN - 1;
            *(uint4*)(AH + r * PPIT + q * 16) = xh4[gn * 8 + q];
            *(uint4*)(AL + r * PPIT + q * 16) = xl4[gn * 8 + q];
        }
        __syncthreads();

        float C[16][4];
        #pragma unroll
        for (int nt = 0; nt < 16; nt++) {
            C[nt][0] = 0.f; C[nt][1] = 0.f; C[nt][2] = 0.f; C[nt][3] = 0.f;
        }

        #pragma unroll
        for (int ks = 0; ks < 4; ks++) {
            unsigned Ah[4], Al4[4];
            ldsm4(Ah[0], Ah[1], Ah[2], Ah[3], aH + ks * 32);
            ldsm4(Al4[0], Al4[1], Al4[2], Al4[3], aL + ks * 32);
            #pragma unroll
            for (int ntp = 0; ntp < 8; ntp++) {
                unsigned Bh[4], Bl[4];
                ldsm4(Bh[0], Bh[1], Bh[2], Bh[3], bH + ntp * 16 * PPIT + ks * 32);
                ldsm4(Bl[0], Bl[1], Bl[2], Bl[3], bL + ntp * 16 * PPIT + ks * 32);
                mma16816(C[2 * ntp],     Ah,  Bh);
                mma16816(C[2 * ntp],     Ah,  Bl);
                mma16816(C[2 * ntp],     Al4, Bh);
                mma16816(C[2 * ntp + 1], Ah,  Bh + 2);
                mma16816(C[2 * ntp + 1], Ah,  Bl + 2);
                mma16816(C[2 * ntp + 1], Al4, Bh + 2);
            }
        }

        int r0 = base + (w << 4) + (l >> 2);
        int r1 = r0 + 8;
        int cc = (l & 3) * 2;
        #pragma unroll
        for (int nt = 0; nt < 8; nt++) {
            int col = nt * 8 + cc;
            if (r0 < NN) *(float2*)(g_p1 + (size_t)r0 * H + col) = make_float2(C[nt][0], C[nt][1]);
            if (r1 < NN) *(float2*)(g_p1 + (size_t)r1 * H + col) = make_float2(C[nt][2], C[nt][3]);
        }
        #pragma unroll
        for (int nt = 8; nt < 16; nt++) {
            int col = (nt - 8) * 8 + cc;
            float2 bb = bias2[nt - 8];
            if (r0 < NN) *(float2*)(g_p2 + (size_t)r0 * H + col) =
                make_float2(C[nt][0] + bb.x, C[nt][1] + bb.y);
            if (r1 < NN) *(float2*)(g_p2 + (size_t)r1 * H + col) =
                make_float2(C[nt][2] + bb.x, C[nt][3] + bb.y);
        }
        __syncthreads();
    }
}

// ---------- CSR edge pass: agg[n] (mean-folded) -> bf16 hi/lo ----------
__global__ __launch_bounds__(NT) void k_edge() {
    int idx = blockIdx.x * NT + threadIdx.x;
    int n = idx >> 3, q = idx & 7;
    int s0 = g_off[n], s1 = g_off[n + 1];
    const float4* p2 = (const float4*)(g_p2 + (size_t)n * H) + q * 2;
    float4 b0 = p2[0], b1 = p2[1];
    float a[8] = {0.f, 0.f, 0.f, 0.f, 0.f, 0.f, 0.f, 0.f};
    for (int i = s0; i < s1; i++) {
        int src = g_csr[i];
        const float4* p1 = (const float4*)(g_p1 + (size_t)src * H) + q * 2;
        float4 c0 = p1[0], c1 = p1[1];
        a[0] += fmaxf(c0.x + b0.x, 0.f); a[1] += fmaxf(c0.y + b0.y, 0.f);
        a[2] += fmaxf(c0.z + b0.z, 0.f); a[3] += fmaxf(c0.w + b0.w, 0.f);
        a[4] += fmaxf(c1.x + b1.x, 0.f); a[5] += fmaxf(c1.y + b1.y, 0.f);
        a[6] += fmaxf(c1.z + b1.z, 0.f); a[7] += fmaxf(c1.w + b1.w, 0.f);
    }
    float ic = 1.0f / fmaxf((float)(s1 - s0), 1.0f);
    __nv_bfloat162 h[4], lo[4];
    #pragma unroll
    for (int j = 0; j < 4; j++) split2(a[2 * j] * ic, a[2 * j + 1] * ic, h[j], lo[j]);
    *(uint2*)(g_ah + (size_t)n * 32 + q * 4)     = *(uint2*)&h[0];
    *(uint2*)(g_ah + (size_t)n * 32 + q * 4 + 2) = *(uint2*)&h[2];
    *(uint2*)(g_al + (size_t)n * 32 + q * 4)     = *(uint2*)&lo[0];
    *(uint2*)(g_al + (size_t)n * 32 + q * 4 + 2) = *(uint2*)&lo[2];
}

// ---------- tensor-core update + residual + LayerNorm ----------
// U[128][64] = [x | agg][128][128] @ W^T; then x = LN(relu(U+b) + x) * g + b2
__global__ __launch_bounds__(256, 2) void k_upd_t(int layer, const float* __restrict__ B,
                                                  const float* __restrict__ lng,
                                                  const float* __restrict__ lnb) {
    extern __shared__ char smc[];
    char* AH = smc;
    char* AL = AH + 128 * UPIT;
    char* BH = AL + 128 * UPIT;
    char* BL = BH + 64 * UPIT;
    float* prm = (float*)(BL + 64 * UPIT);   // bias[64], g[64], b2[64]

    const int tid = threadIdx.x;
    const int w = tid >> 5, l = tid & 31;

    {
        const uint4* sh = (const uint4*)(g_uh + layer * 64 * 136);
        const uint4* sl = (const uint4*)(g_ul + layer * 64 * 136);
        for (int i = tid; i < 1088; i += 256) {
            ((uint4*)BH)[i] = sh[i];
            ((uint4*)BL)[i] = sl[i];
        }
        if (tid < 64) {
            prm[tid] = B[tid];
            prm[64 + tid] = lng[tid];
            prm[128 + tid] = lnb[tid];
        }
    }

    const uint32_t a_loff = (uint32_t)(((w << 4) + (l & 15)) * UPIT) + ((l >> 4) ? 16u : 0u);
    const uint32_t b_loff = (uint32_t)((l & 7) * UPIT) + (((l >> 3) & 1) ? 16u : 0u)
                          + (((l >> 4) & 1) ? 8u * UPIT : 0u);
    const uint32_t aH = (uint32_t)__cvta_generic_to_shared(AH) + a_loff;
    const uint32_t aL = (uint32_t)__cvta_generic_to_shared(AL) + a_loff;
    const uint32_t bH = (uint32_t)__cvta_generic_to_shared(BH) + b_loff;
    const uint32_t bL = (uint32_t)__cvta_generic_to_shared(BL) + b_loff;

    const uint4* xh4 = (const uint4*)g_xh;
    const uint4* xl4 = (const uint4*)g_xl;
    const uint4* ah4 = (const uint4*)g_ah;
    const uint4* al4 = (const uint4*)g_al;

    const int ntiles = (NN + 127) / 128;
    for (int tile = blockIdx.x; tile < ntiles; tile += gridDim.x) {
        const int base = tile * 128;

        // stage A: [x chunks 0-7 | agg chunks 8-15] per row, hi and lo
        for (int i = tid; i < 2048; i += 256) {
            int r = i >> 4, q = i & 15;
            int gn = base + r; if (gn >= NN) gn = NN - 1;
            uint4 vh = (q < 8) ? xh4[gn * 8 + q] : ah4[gn * 8 + (q - 8)];
            uint4 vl = (q < 8) ? xl4[gn * 8 + q] : al4[gn * 8 + (q - 8)];
            *(uint4*)(AH + r * UPIT + q * 16) = vh;
            *(uint4*)(AL + r * UPIT + q * 16) = vl;
        }
        __syncthreads();

        float C[8][4];
        #pragma unroll
        for (int nt = 0; nt < 8; nt++) {
            C[nt][0] = 0.f; C[nt][1] = 0.f; C[nt][2] = 0.f; C[nt][3] = 0.f;
        }

        #pragma unroll
        for (int ks = 0; ks < 8; ks++) {
            unsigned Ah[4], Al4r[4];
            ldsm4(Ah[0], Ah[1], Ah[2], Ah[3], aH + ks * 32);
            ldsm4(Al4r[0], Al4r[1], Al4r[2], Al4r[3], aL + ks * 32);
            #pragma unroll
            for (int ntp = 0; ntp < 4; ntp++) {
                unsigned Bh[4], Bl[4];
                ldsm4(Bh[0], Bh[1], Bh[2], Bh[3], bH + ntp * 16 * UPIT + ks * 32);
                ldsm4(Bl[0], Bl[1], Bl[2], Bl[3], bL + ntp * 16 * UPIT + ks * 32);
                mma16816(C[2 * ntp],     Ah,   Bh);
                mma16816(C[2 * ntp],     Ah,   Bl);
                mma16816(C[2 * ntp],     Al4r, Bh);
                mma16816(C[2 * ntp + 1], Ah,   Bh + 2);
                mma16816(C[2 * ntp + 1], Ah,   Bl + 2);
                mma16816(C[2 * ntp + 1], Al4r, Bh + 2);
            }
        }

        // epilogue: relu + bias + residual + LN over 64 cols (4 lanes/row)
        int rr0 = base + (w << 4) + (l >> 2);
        int rr1 = rr0 + 8;
        int r0c = rr0 < NN ? rr0 : NN - 1;
        int r1c = rr1 < NN ? rr1 : NN - 1;
        int cc = (l & 3) * 2;
        float h0[8], h1[8];
        float s1a = 0.f, s2a = 0.f, s1b = 0.f, s2b = 0.f;
        #pragma unroll
        for (int nt = 0; nt < 8; nt++) {
            int col = nt * 8 + cc;
            float bx = prm[col], by = prm[col + 1];
            float2 xa = *(const float2*)(g_x + (size_t)r0c * H + col);
            float2 xb = *(const float2*)(g_x + (size_t)r1c * H + col);
            float v0 = fmaxf(C[nt][0] + bx, 0.f) + xa.x;
            float v1 = fmaxf(C[nt][1] + by, 0.f) + xa.y;
            float v2 = fmaxf(C[nt][2] + bx, 0.f) + xb.x;
            float v3 = fmaxf(C[nt][3] + by, 0.f) + xb.y;
            h0[nt] = v0; h1[nt] = v2;
            s1a += v0 + v1; s2a += v0 * v0 + v1 * v1;
            s1b += v2 + v3; s2b += v2 * v2 + v3 * v3;
            C[nt][1] = v1; C[nt][3] = v3;   // reuse storage
        }
        #pragma unroll
        for (int d = 1; d < 4; d <<= 1) {
            s1a += __shfl_xor_sync(0xFFFFFFFFu, s1a, d);
            s2a += __shfl_xor_sync(0xFFFFFFFFu, s2a, d);
            s1b += __shfl_xor_sync(0xFFFFFFFFu, s1b, d);
            s2b += __shfl_xor_sync(0xFFFFFFFFu, s2b, d);
        }
        float mua = s1a * 0.015625f, mub = s1b * 0.015625f;
        float sca = rsqrtf(fmaxf(s2a * 0.015625f - mua * mua, 0.f) + 1e-5f);
        float scb = rsqrtf(fmaxf(s2b * 0.015625f - mub * mub, 0.f) + 1e-5f);
        #pragma unroll
        for (int nt = 0; nt < 8; nt++) {
            int col = nt * 8 + cc;
            float gx = prm[64 + col], gy = prm[65 + col];
            float bx = prm[128 + col], by = prm[129 + col];
            if (rr0 < NN) {
                float o0 = (h0[nt] - mua) * sca * gx + bx;
                float o1 = (C[nt][1] - mua) * sca * gy + by;
                *(float2*)(g_x + (size_t)rr0 * H + col) = make_float2(o0, o1);
                __nv_bfloat162 hh, ll;
                split2(o0, o1, hh, ll);
                g_xh[(size_t)rr0 * 32 + (col >> 1)] = hh;
                g_xl[(size_t)rr0 * 32 + (col >> 1)] = ll;
            }
            if (rr1 < NN) {
                float o2 = (h1[nt] - mub) * scb * gx + bx;
                float o3 = (C[nt][3] - mub) * scb * gy + by;
                *(float2*)(g_x + (size_t)rr1 * H + col) = make_float2(o2, o3);
                __nv_bfloat162 hh, ll;
                split2(o2, o3, hh, ll);
                g_xh[(size_t)rr1 * 32 + (col >> 1)] = hh;
                g_xl[(size_t)rr1 * 32 + (col >> 1)] = ll;
            }
        }
        __syncthreads();
    }
}

// ---------- final mean/max over nodes ----------
__global__ void k_reduce() {
    __shared__ float rs[4][64];
    __shared__ float rm[4][64];
    int j = threadIdx.x & 63, g = threadIdx.x >> 6;
    float s = 0.f, m = -3.402823466e38f;
    for (int n = blockIdx.x * 4 + g; n < NN; n += gridDim.x * 4) {
        float v = g_x[(size_t)n * H + j];
        s += v; m = fmaxf(m, v);
    }
    rs[g][j] = s; rm[g][j] = m;
    __syncthreads();
    if (g == 0) {
        #pragma unroll
        for (int i = 1; i < 4; i++) { s += rs[i][j]; m = fmaxf(m, rm[i][j]); }
        atomicAdd(&g_sum[j], s);
        atomicMax(&g_maxb[j], encf(m));
    }
}

__global__ void k_final(float* out) {
    int t = threadIdx.x;
    if (t < 64) out[t] = g_sum[t] * (1.0f / NN);
    else        out[t] = decf(g_maxb[t - 64]);
}

// ---------- launch ----------
extern "C" void kernel_launch(void* const* d_in, const int* in_sizes, int n_in,
                              void* d_out, int out_size) {
    const int*   ti    = (const int*)d_in[0];
    const int*   edges = (const int*)d_in[1];
    const float* et    = (const float*)d_in[2];
    const float* msg_w = (const float*)d_in[3];
    const float* msg_b = (const float*)d_in[4];
    const float* upd_w = (const float*)d_in[5];
    const float* upd_b = (const float*)d_in[6];
    const float* lng   = (const float*)d_in[7];
    const float* lnb   = (const float*)d_in[8];
    float* out = (float*)d_out;

    cudaFuncSetAttribute(k_proj_t, cudaFuncAttributeMaxDynamicSharedMemorySize, SMEM_PROJT);
    cudaFuncSetAttribute(k_upd_t,  cudaFuncAttributeMaxDynamicSharedMemorySize, SMEM_UPDT);

    k_embed<<<512, 256>>>(ti, et);
    k_hist<<<512, 256>>>(edges);
    k_prepack<<<96, 256>>>(msg_w, upd_w);

    // layer-0 proj placed 4th so ncu (-s5 -c1) profiles it
    k_proj_t<<<296, 256, SMEM_PROJT>>>(0, msg_b);

    k_scan1<<<NBLK, 256>>>();
    k_scan2<<<1, 512>>>();
    k_scan3<<<392, 256>>>();
    k_scatter<<<(NE + 255) / 256, 256>>>(edges);

    for (int l = 0; l < 3; l++) {
        if (l > 0) k_proj_t<<<296, 256, SMEM_PROJT>>>(l, msg_b + l * 64);
        k_edge<<<NN * 8 / NT, NT>>>();
        k_upd_t<<<296, 256, SMEM_UPDT>>>(l, upd_b + l * 64, lng + l * 64, lnb + l * 64);
    }

    k_reduce<<<296, 256>>>();
    k_final<<<1, 128>>>(out);
}

// round 11
// speedup vs baseline: 1.6798x; 1.0261x over previous
#include <cuda_runtime.h>
#include <cuda_bf16.h>
#include <cstdint>

#define NN 100000
#define NE 800000
#define H  64
#define NT 256
#define NBLK 391
#define PPIT 144   // proj smem row pitch bytes (72 bf16)
#define UPIT 272   // upd smem row pitch bytes (136 bf16)

#define SMEM_PROJT (4 * 128 * PPIT)                         // AH AL BH BL
#define SMEM_UPDT  (2 * 128 * UPIT + 2 * 64 * UPIT + 768)   // AH AL BH BL + params

// Scratch (device globals: allocation-free rule)
__device__ __align__(16) float g_x[(size_t)NN * H];
__device__ __align__(16) float g_p1[(size_t)NN * H];
__device__ __align__(16) float g_p2[(size_t)NN * H];
__device__ __align__(16) __nv_bfloat162 g_xh[(size_t)NN * 32];
__device__ __align__(16) __nv_bfloat162 g_xl[(size_t)NN * 32];
__device__ __align__(16) __nv_bfloat162 g_ah[(size_t)NN * 32];
__device__ __align__(16) __nv_bfloat162 g_al[(size_t)NN * 32];
__device__ __align__(16) __nv_bfloat16 g_bh[3 * 128 * 72];   // proj W hi [C][k] pitch 72
__device__ __align__(16) __nv_bfloat16 g_bl[3 * 128 * 72];
__device__ __align__(16) __nv_bfloat16 g_uh[3 * 64 * 136];   // upd W hi [C][k] pitch 136
__device__ __align__(16) __nv_bfloat16 g_ul[3 * 64 * 136];
__device__ int g_deg[NN];
__device__ int g_off[NN + 1];
__device__ int g_cur[NN];
__device__ int g_csr[NE];
__device__ int g_bsum[NBLK];
__device__ int g_boff[NBLK];
__device__ float g_sum[H];
__device__ unsigned g_maxb[H];

// ---------- helpers ----------
__device__ __forceinline__ unsigned encf(float f) {
    unsigned u = __float_as_uint(f);
    return (u & 0x80000000u) ? ~u : (u | 0x80000000u);
}
__device__ __forceinline__ float decf(unsigned u) {
    return (u & 0x80000000u) ? __uint_as_float(u & 0x7FFFFFFFu) : __uint_as_float(~u);
}
__device__ __forceinline__ void split2(float a, float b, __nv_bfloat162& h, __nv_bfloat162& lo) {
    __nv_bfloat16 ha = __float2bfloat16(a), hb = __float2bfloat16(b);
    h = __halves2bfloat162(ha, hb);
    lo = __halves2bfloat162(__float2bfloat16(a - __bfloat162float(ha)),
                            __float2bfloat16(b - __bfloat162float(hb)));
}
__device__ __forceinline__ void ldsm4(unsigned& r0, unsigned& r1, unsigned& r2, unsigned& r3,
                                      uint32_t addr) {
    asm volatile("ldmatrix.sync.aligned.m8n8.x4.shared.b16 {%0,%1,%2,%3}, [%4];"
                 : "=r"(r0), "=r"(r1), "=r"(r2), "=r"(r3) : "r"(addr));
}
__device__ __forceinline__ void mma16816(float* c, const unsigned* a, const unsigned* b) {
    asm volatile("mma.sync.aligned.m16n8k16.row.col.f32.bf16.bf16.f32 "
                 "{%0,%1,%2,%3}, {%4,%5,%6,%7}, {%8,%9}, {%0,%1,%2,%3};"
                 : "+f"(c[0]), "+f"(c[1]), "+f"(c[2]), "+f"(c[3])
                 : "r"(a[0]), "r"(a[1]), "r"(a[2]), "r"(a[3]), "r"(b[0]), "r"(b[1]));
}
__device__ __forceinline__ void cpa16(void* dst, const void* src) {
    unsigned d = (unsigned)__cvta_generic_to_shared(dst);
    asm volatile("cp.async.ca.shared.global [%0], [%1], 16;" :: "r"(d), "l"(src));
}
#define CPA_COMMIT() asm volatile("cp.async.commit_group;")
#define CPA_WAIT0()  asm volatile("cp.async.wait_group 0;")

// ---------- merged setup: embed + hist + weight prepack ----------
__global__ void k_setup(const int* __restrict__ ti, const float* __restrict__ et,
                        const int* __restrict__ edges,
                        const float* __restrict__ msg_w, const float* __restrict__ upd_w) {
    int i = blockIdx.x * blockDim.x + threadIdx.x;
    int stride = gridDim.x * blockDim.x;
    for (int lin = i; lin < NN * 16; lin += stride) {
        int n = lin >> 4, q = lin & 15;
        float4 v = ((const float4*)et)[ti[n] * 16 + q];
        ((float4*)g_x)[lin] = v;
        __nv_bfloat162 h0, l0, h1, l1;
        split2(v.x, v.y, h0, l0);
        split2(v.z, v.w, h1, l1);
        g_xh[lin * 2] = h0; g_xh[lin * 2 + 1] = h1;
        g_xl[lin * 2] = l0; g_xl[lin * 2 + 1] = l1;
    }
    for (int n = i; n < NN; n += stride) g_deg[n] = 0;
    if (i < H) { g_sum[i] = 0.f; g_maxb[i] = 0u; }
    // prepack weights (bf16 hi/lo, n-major, padded pitch)
    for (int idx = i; idx < 3 * 128 * 72; idx += stride) {
        int l = idx / (128 * 72), r = idx % (128 * 72);
        int C = r / 72, k = r % 72;
        __nv_bfloat16 h = __float2bfloat16(0.f), lo = h;
        if (k < 64) {
            float v = msg_w[l * 8192 + (k + (C & 64)) * 64 + (C & 63)];
            h = __float2bfloat16(v);
            lo = __float2bfloat16(v - __bfloat162float(h));
        }
        g_bh[idx] = h; g_bl[idx] = lo;
    }
    for (int idx = i; idx < 3 * 64 * 136; idx += stride) {
        int l = idx / (64 * 136), r = idx % (64 * 136);
        int C = r / 136, k = r % 136;
        __nv_bfloat16 h = __float2bfloat16(0.f), lo = h;
        if (k < 128) {
            float v = upd_w[l * 8192 + k * 64 + C];
            h = __float2bfloat16(v);
            lo = __float2bfloat16(v - __bfloat162float(h));
        }
        g_uh[idx] = h; g_ul[idx] = lo;
    }
}

__global__ void k_hist(const int* __restrict__ edges) {
    int i = blockIdx.x * blockDim.x + threadIdx.x;
    int stride = gridDim.x * blockDim.x;
    for (int e = i; e < NE; e += stride)
        atomicAdd(&g_deg[((const int2*)edges)[e].y], 1);
}

// ---------- exclusive scan ----------
__global__ void k_scan1() {
    __shared__ int s[256];
    int t = threadIdx.x;
    int i = blockIdx.x * 256 + t;
    int v = (i < NN) ? g_deg[i] : 0;
    s[t] = v;
    __syncthreads();
    #pragma unroll
    for (int d = 1; d < 256; d <<= 1) {
        int tv = (t >= d) ? s[t - d] : 0;
        __syncthreads();
        s[t] += tv;
        __syncthreads();
    }
    if (i < NN) g_off[i] = s[t] - v;
    if (t == 255) g_bsum[blockIdx.x] = s[255];
}

__global__ void k_scan2() {
    __shared__ int s[512];
    int t = threadIdx.x;
    int v = (t < NBLK) ? g_bsum[t] : 0;
    s[t] = v;
    __syncthreads();
    #pragma unroll
    for (int d = 1; d < 512; d <<= 1) {
        int tv = (t >= d) ? s[t - d] : 0;
        __syncthreads();
        s[t] += tv;
        __syncthreads();
    }
    if (t < NBLK) g_boff[t] = s[t] - v;
}

__global__ void k_scan3() {
    int i = blockIdx.x * blockDim.x + threadIdx.x;
    if (i < NN) {
        int val = g_off[i] + g_boff[i >> 8];
        g_off[i] = val;
        g_cur[i] = val;
    }
    if (i == 0) g_off[NN] = NE;
}

__global__ void k_scatter(const int* __restrict__ edges) {
    int e = blockIdx.x * blockDim.x + threadIdx.x;
    if (e < NE) {
        int2 ed = ((const int2*)edges)[e];
        int pos = atomicAdd(&g_cur[ed.y], 1);
        g_csr[pos] = ed.x;
    }
}

// ---------- tensor-core projection (cp.async pipelined) ----------
__global__ __launch_bounds__(256, 2) void k_proj_t(int layer, const float* __restrict__ msg_b) {
    extern __shared__ char smc[];
    char* AH = smc;
    char* AL = AH + 128 * PPIT;
    char* BH = AL + 128 * PPIT;
    char* BL = BH + 128 * PPIT;

    const int tid = threadIdx.x;
    const int w = tid >> 5, l = tid & 31;

    {
        const uint4* sh = (const uint4*)(g_bh + layer * 128 * 72);
        const uint4* sl = (const uint4*)(g_bl + layer * 128 * 72);
        for (int i = tid; i < 1152; i += 256) {
            ((uint4*)BH)[i] = sh[i];
            ((uint4*)BL)[i] = sl[i];
        }
    }
    float2 bias2[8];
    #pragma unroll
    for (int i = 0; i < 8; i++) bias2[i] = *(const float2*)(msg_b + i * 8 + (l & 3) * 2);

    const uint32_t a_loff = (uint32_t)(((w << 4) + (l & 15)) * PPIT) + ((l >> 4) ? 16u : 0u);
    const uint32_t b_loff = (uint32_t)((l & 7) * PPIT) + (((l >> 3) & 1) ? 16u : 0u)
                          + (((l >> 4) & 1) ? 8u * PPIT : 0u);
    const uint32_t aH = (uint32_t)__cvta_generic_to_shared(AH) + a_loff;
    const uint32_t aL = (uint32_t)__cvta_generic_to_shared(AL) + a_loff;
    const uint32_t bH = (uint32_t)__cvta_generic_to_shared(BH) + b_loff;
    const uint32_t bL = (uint32_t)__cvta_generic_to_shared(BL) + b_loff;

    const uint4* xh4 = (const uint4*)g_xh;
    const uint4* xl4 = (const uint4*)g_xl;

    const int ntiles = (NN + 127) / 128;

    // A staging via cp.async: 4 (AH) + 4 (AL) chunks per thread
    auto stageA = [&](int base) {
        #pragma unroll
        for (int s = 0; s < 4; s++) {
            int i = s * 256 + tid;
            int r = i >> 3, q = i & 7;
            int gn = base + r; if (gn >= NN) gn = NN - 1;
            cpa16(AH + r * PPIT + q * 16, &xh4[gn * 8 + q]);
            cpa16(AL + r * PPIT + q * 16, &xl4[gn * 8 + q]);
        }
    };

    if (blockIdx.x < ntiles) stageA(blockIdx.x * 128);
    CPA_COMMIT();

    for (int tile = blockIdx.x; tile < ntiles; tile += gridDim.x) {
        const int base = tile * 128;
        CPA_WAIT0();
        __syncthreads();   // A (and B on first iter) visible to all

        float C[16][4];
        #pragma unroll
        for (int nt = 0; nt < 16; nt++) {
            C[nt][0] = 0.f; C[nt][1] = 0.f; C[nt][2] = 0.f; C[nt][3] = 0.f;
        }

        #pragma unroll
        for (int ks = 0; ks < 4; ks++) {
            unsigned Ah[4], Al4[4];
            ldsm4(Ah[0], Ah[1], Ah[2], Ah[3], aH + ks * 32);
            ldsm4(Al4[0], Al4[1], Al4[2], Al4[3], aL + ks * 32);
            #pragma unroll
            for (int ntp = 0; ntp < 8; ntp++) {
                unsigned Bh[4], Bl[4];
                ldsm4(Bh[0], Bh[1], Bh[2], Bh[3], bH + ntp * 16 * PPIT + ks * 32);
                ldsm4(Bl[0], Bl[1], Bl[2], Bl[3], bL + ntp * 16 * PPIT + ks * 32);
                mma16816(C[2 * ntp],     Ah,  Bh);
                mma16816(C[2 * ntp],     Ah,  Bl);
                mma16816(C[2 * ntp],     Al4, Bh);
                mma16816(C[2 * ntp + 1], Ah,  Bh + 2);
                mma16816(C[2 * ntp + 1], Ah,  Bl + 2);
                mma16816(C[2 * ntp + 1], Al4, Bh + 2);
            }
        }
        __syncthreads();   // all A-smem reads complete

        int nxt = tile + gridDim.x;
        if (nxt < ntiles) stageA(nxt * 128);
        CPA_COMMIT();

        // epilogue overlaps the async staging
        int r0 = base + (w << 4) + (l >> 2);
        int r1 = r0 + 8;
        int cc = (l & 3) * 2;
        #pragma unroll
        for (int nt = 0; nt < 8; nt++) {
            int col = nt * 8 + cc;
            if (r0 < NN) *(float2*)(g_p1 + (size_t)r0 * H + col) = make_float2(C[nt][0], C[nt][1]);
            if (r1 < NN) *(float2*)(g_p1 + (size_t)r1 * H + col) = make_float2(C[nt][2], C[nt][3]);
        }
        #pragma unroll
        for (int nt = 8; nt < 16; nt++) {
            int col = (nt - 8) * 8 + cc;
            float2 bb = bias2[nt - 8];
            if (r0 < NN) *(float2*)(g_p2 + (size_t)r0 * H + col) =
                make_float2(C[nt][0] + bb.x, C[nt][1] + bb.y);
            if (r1 < NN) *(float2*)(g_p2 + (size_t)r1 * H + col) =
                make_float2(C[nt][2] + bb.x, C[nt][3] + bb.y);
        }
    }
}

// ---------- CSR edge pass: agg[n] (mean-folded) -> bf16 hi/lo ----------
__global__ __launch_bounds__(NT) void k_edge() {
    int idx = blockIdx.x * NT + threadIdx.x;
    int n = idx >> 3, q = idx & 7;
    int s0 = g_off[n], s1 = g_off[n + 1];
    const float4* p2 = (const float4*)(g_p2 + (size_t)n * H) + q * 2;
    float4 b0 = p2[0], b1 = p2[1];
    float a[8] = {0.f, 0.f, 0.f, 0.f, 0.f, 0.f, 0.f, 0.f};
    for (int i = s0; i < s1; i++) {
        int src = g_csr[i];
        const float4* p1 = (const float4*)(g_p1 + (size_t)src * H) + q * 2;
        float4 c0 = p1[0], c1 = p1[1];
        a[0] += fmaxf(c0.x + b0.x, 0.f); a[1] += fmaxf(c0.y + b0.y, 0.f);
        a[2] += fmaxf(c0.z + b0.z, 0.f); a[3] += fmaxf(c0.w + b0.w, 0.f);
        a[4] += fmaxf(c1.x + b1.x, 0.f); a[5] += fmaxf(c1.y + b1.y, 0.f);
        a[6] += fmaxf(c1.z + b1.z, 0.f); a[7] += fmaxf(c1.w + b1.w, 0.f);
    }
    float ic = 1.0f / fmaxf((float)(s1 - s0), 1.0f);
    __nv_bfloat162 h[4], lo[4];
    #pragma unroll
    for (int j = 0; j < 4; j++) split2(a[2 * j] * ic, a[2 * j + 1] * ic, h[j], lo[j]);
    *(uint4*)(g_ah + (size_t)n * 32 + q * 4) = *(uint4*)h;
    *(uint4*)(g_al + (size_t)n * 32 + q * 4) = *(uint4*)lo;
}

// ---------- tensor-core update + residual + LayerNorm (cp.async pipelined) ----------
__global__ __launch_bounds__(256, 2) void k_upd_t(int layer, const float* __restrict__ B,
                                                  const float* __restrict__ lng,
                                                  const float* __restrict__ lnb) {
    extern __shared__ char smc[];
    char* AH = smc;
    char* AL = AH + 128 * UPIT;
    char* BH = AL + 128 * UPIT;
    char* BL = BH + 64 * UPIT;
    float* prm = (float*)(BL + 64 * UPIT);

    const int tid = threadIdx.x;
    const int w = tid >> 5, l = tid & 31;

    {
        const uint4* sh = (const uint4*)(g_uh + layer * 64 * 136);
        const uint4* sl = (const uint4*)(g_ul + layer * 64 * 136);
        for (int i = tid; i < 1088; i += 256) {
            ((uint4*)BH)[i] = sh[i];
            ((uint4*)BL)[i] = sl[i];
        }
        if (tid < 64) {
            prm[tid] = B[tid];
            prm[64 + tid] = lng[tid];
            prm[128 + tid] = lnb[tid];
        }
    }

    const uint32_t a_loff = (uint32_t)(((w << 4) + (l & 15)) * UPIT) + ((l >> 4) ? 16u : 0u);
    const uint32_t b_loff = (uint32_t)((l & 7) * UPIT) + (((l >> 3) & 1) ? 16u : 0u)
                          + (((l >> 4) & 1) ? 8u * UPIT : 0u);
    const uint32_t aH = (uint32_t)__cvta_generic_to_shared(AH) + a_loff;
    const uint32_t aL = (uint32_t)__cvta_generic_to_shared(AL) + a_loff;
    const uint32_t bH = (uint32_t)__cvta_generic_to_shared(BH) + b_loff;
    const uint32_t bL = (uint32_t)__cvta_generic_to_shared(BL) + b_loff;

    const uint4* xh4 = (const uint4*)g_xh;
    const uint4* xl4 = (const uint4*)g_xl;
    const uint4* ah4 = (const uint4*)g_ah;
    const uint4* al4 = (const uint4*)g_al;

    const int ntiles = (NN + 127) / 128;

    auto stageA = [&](int base) {
        #pragma unroll
        for (int s = 0; s < 8; s++) {
            int i = s * 256 + tid;
            int r = i >> 4, q = i & 15;
            int gn = base + r; if (gn >= NN) gn = NN - 1;
            const uint4* srch = (q < 8) ? &xh4[gn * 8 + q] : &ah4[gn * 8 + (q - 8)];
            const uint4* srcl = (q < 8) ? &xl4[gn * 8 + q] : &al4[gn * 8 + (q - 8)];
            cpa16(AH + r * UPIT + q * 16, srch);
            cpa16(AL + r * UPIT + q * 16, srcl);
        }
    };

    if (blockIdx.x < ntiles) stageA(blockIdx.x * 128);
    CPA_COMMIT();

    for (int tile = blockIdx.x; tile < ntiles; tile += gridDim.x) {
        const int base = tile * 128;
        CPA_WAIT0();
        __syncthreads();

        float C[8][4];
        #pragma unroll
        for (int nt = 0; nt < 8; nt++) {
            C[nt][0] = 0.f; C[nt][1] = 0.f; C[nt][2] = 0.f; C[nt][3] = 0.f;
        }

        #pragma unroll
        for (int ks = 0; ks < 8; ks++) {
            unsigned Ah[4], Al4r[4];
            ldsm4(Ah[0], Ah[1], Ah[2], Ah[3], aH + ks * 32);
            ldsm4(Al4r[0], Al4r[1], Al4r[2], Al4r[3], aL + ks * 32);
            #pragma unroll
            for (int ntp = 0; ntp < 4; ntp++) {
                unsigned Bh[4], Bl[4];
                ldsm4(Bh[0], Bh[1], Bh[2], Bh[3], bH + ntp * 16 * UPIT + ks * 32);
                ldsm4(Bl[0], Bl[1], Bl[2], Bl[3], bL + ntp * 16 * UPIT + ks * 32);
                mma16816(C[2 * ntp],     Ah,   Bh);
                mma16816(C[2 * ntp],     Ah,   Bl);
                mma16816(C[2 * ntp],     Al4r, Bh);
                mma16816(C[2 * ntp + 1], Ah,   Bh + 2);
                mma16816(C[2 * ntp + 1], Ah,   Bl + 2);
                mma16816(C[2 * ntp + 1], Al4r, Bh + 2);
            }
        }
        __syncthreads();   // all A-smem reads complete

        int nxt = tile + gridDim.x;
        if (nxt < ntiles) stageA(nxt * 128);
        CPA_COMMIT();

        // epilogue (gmem + prm only) overlaps staging
        int rr0 = base + (w << 4) + (l >> 2);
        int rr1 = rr0 + 8;
        int r0c = rr0 < NN ? rr0 : NN - 1;
        int r1c = rr1 < NN ? rr1 : NN - 1;
        int cc = (l & 3) * 2;
        float h0[8], h1[8];
        float s1a = 0.f, s2a = 0.f, s1b = 0.f, s2b = 0.f;
        #pragma unroll
        for (int nt = 0; nt < 8; nt++) {
            int col = nt * 8 + cc;
            float bx = prm[col], by = prm[col + 1];
            float2 xa = *(const float2*)(g_x + (size_t)r0c * H + col);
            float2 xb = *(const float2*)(g_x + (size_t)r1c * H + col);
            float v0 = fmaxf(C[nt][0] + bx, 0.f) + xa.x;
            float v1 = fmaxf(C[nt][1] + by, 0.f) + xa.y;
            float v2 = fmaxf(C[nt][2] + bx, 0.f) + xb.x;
            float v3 = fmaxf(C[nt][3] + by, 0.f) + xb.y;
            h0[nt] = v0; h1[nt] = v2;
            s1a += v0 + v1; s2a += v0 * v0 + v1 * v1;
            s1b += v2 + v3; s2b += v2 * v2 + v3 * v3;
            C[nt][1] = v1; C[nt][3] = v3;
        }
        #pragma unroll
        for (int d = 1; d < 4; d <<= 1) {
            s1a += __shfl_xor_sync(0xFFFFFFFFu, s1a, d);
            s2a += __shfl_xor_sync(0xFFFFFFFFu, s2a, d);
            s1b += __shfl_xor_sync(0xFFFFFFFFu, s1b, d);
            s2b += __shfl_xor_sync(0xFFFFFFFFu, s2b, d);
        }
        float mua = s1a * 0.015625f, mub = s1b * 0.015625f;
        float sca = rsqrtf(fmaxf(s2a * 0.015625f - mua * mua, 0.f) + 1e-5f);
        float scb = rsqrtf(fmaxf(s2b * 0.015625f - mub * mub, 0.f) + 1e-5f);
        #pragma unroll
        for (int nt = 0; nt < 8; nt++) {
            int col = nt * 8 + cc;
            float gx = prm[64 + col], gy = prm[65 + col];
            float bx = prm[128 + col], by = prm[129 + col];
            if (rr0 < NN) {
                float o0 = (h0[nt] - mua) * sca * gx + bx;
                float o1 = (C[nt][1] - mua) * sca * gy + by;
                *(float2*)(g_x + (size_t)rr0 * H + col) = make_float2(o0, o1);
                __nv_bfloat162 hh, ll;
                split2(o0, o1, hh, ll);
                g_xh[(size_t)rr0 * 32 + (col >> 1)] = hh;
                g_xl[(size_t)rr0 * 32 + (col >> 1)] = ll;
            }
            if (rr1 < NN) {
                float o2 = (h1[nt] - mub) * scb * gx + bx;
                float o3 = (C[nt][3] - mub) * scb * gy + by;
                *(float2*)(g_x + (size_t)rr1 * H + col) = make_float2(o2, o3);
                __nv_bfloat162 hh, ll;
                split2(o2, o3, hh, ll);
                g_xh[(size_t)rr1 * 32 + (col >> 1)] = hh;
                g_xl[(size_t)rr1 * 32 + (col >> 1)] = ll;
            }
        }
    }
}

// ---------- final mean/max over nodes ----------
__global__ void k_reduce() {
    __shared__ float rs[4][64];
    __shared__ float rm[4][64];
    int j = threadIdx.x & 63, g = threadIdx.x >> 6;
    float s = 0.f, m = -3.402823466e38f;
    for (int n = blockIdx.x * 4 + g; n < NN; n += gridDim.x * 4) {
        float v = g_x[(size_t)n * H + j];
        s += v; m = fmaxf(m, v);
    }
    rs[g][j] = s; rm[g][j] = m;
    __syncthreads();
    if (g == 0) {
        #pragma unroll
        for (int i = 1; i < 4; i++) { s += rs[i][j]; m = fmaxf(m, rm[i][j]); }
        atomicAdd(&g_sum[j], s);
        atomicMax(&g_maxb[j], encf(m));
    }
}

__global__ void k_final(float* out) {
    int t = threadIdx.x;
    if (t < 64) out[t] = g_sum[t] * (1.0f / NN);
    else        out[t] = decf(g_maxb[t - 64]);
}

// ---------- launch ----------
extern "C" void kernel_launch(void* const* d_in, const int* in_sizes, int n_in,
                              void* d_out, int out_size) {
    const int*   ti    = (const int*)d_in[0];
    const int*   edges = (const int*)d_in[1];
    const float* et    = (const float*)d_in[2];
    const float* msg_w = (const float*)d_in[3];
    const float* msg_b = (const float*)d_in[4];
    const float* upd_w = (const float*)d_in[5];
    const float* upd_b = (const float*)d_in[6];
    const float* lng   = (const float*)d_in[7];
    const float* lnb   = (const float*)d_in[8];
    float* out = (float*)d_out;

    cudaFuncSetAttribute(k_proj_t, cudaFuncAttributeMaxDynamicSharedMemorySize, SMEM_PROJT);
    cudaFuncSetAttribute(k_upd_t,  cudaFuncAttributeMaxDynamicSharedMemorySize, SMEM_UPDT);

    k_setup<<<512, 256>>>(ti, et, edges, msg_w, upd_w);
    k_hist<<<512, 256>>>(edges);
    k_scan1<<<NBLK, 256>>>();
    // layer-0 proj placed 4th so ncu (-s5 -c1) profiles it
    k_proj_t<<<296, 256, SMEM_PROJT>>>(0, msg_b);
    k_scan2<<<1, 512>>>();
    k_scan3<<<392, 256>>>();
    k_scatter<<<(NE + 255) / 256, 256>>>(edges);

    for (int l = 0; l < 3; l++) {
        if (l > 0) k_proj_t<<<296, 256, SMEM_PROJT>>>(l, msg_b + l * 64);
        k_edge<<<NN * 8 / NT, NT>>>();
        k_upd_t<<<296, 256, SMEM_UPDT>>>(l, upd_b + l * 64, lng + l * 64, lnb + l * 64);
    }

    k_reduce<<<296, 256>>>();
    k_final<<<1, 128>>>(out);
}